// round 17
// baseline (speedup 1.0000x reference)
#include <cuda_runtime.h>

// out[h1,w1,c1,h2,w2,c2] = g^(|dh|+|dw|+|dc|) * (1 + spec_pe[c1,c2]*mean[h1,w1,c1]) * decay[c1]
// mean[h1,w1,c1] = Sh[h1]*Sw[w1]*Sc[c1] / (H*W*C), closed-form geometric sums.
// H=W=32, C=8. Output: 1024 * 65536 floats = 268.4 MB, pure write-bound.
//
// R17 = R16 (closed-form setup + STG.256 .wt, best bench 42.53us) with
// 1024-thread CTAs covering one full (h1,w1) tile: exactly one thread per
// (h2,w2) row. Setup+barrier executed 1024x instead of 2048x (no duplicate
// coef computation), same 64 resident warps/SM (30 regs -> 2 CTAs/SM).

#define GAMMA 0.9f
#define INV_1MG (1.0f / (1.0f - GAMMA))   // 10

__device__ __forceinline__ void stg256wt(float* p, float x0, float x1, float x2, float x3,
                                         float x4, float x5, float x6, float x7) {
    asm volatile("st.global.wt.v8.b32 [%0], {%1,%2,%3,%4,%5,%6,%7,%8};"
                 :: "l"(p),
                    "r"(__float_as_uint(x0)), "r"(__float_as_uint(x1)),
                    "r"(__float_as_uint(x2)), "r"(__float_as_uint(x3)),
                    "r"(__float_as_uint(x4)), "r"(__float_as_uint(x5)),
                    "r"(__float_as_uint(x6)), "r"(__float_as_uint(x7))
                 : "memory");
}

// Sum_{j=0}^{N-1} gamma^|x-j| in closed form
__device__ __forceinline__ float geosum(int x, int N) {
    return ((1.0f - __powf(GAMMA, (float)(x + 1))) +
            (GAMMA - __powf(GAMMA, (float)(N - x)))) * INV_1MG;
}

__global__ __launch_bounds__(1024) void mrp3d_kernel(const float* __restrict__ decay,
                                                     const float* __restrict__ spec_pe,
                                                     float* __restrict__ out) {
    __shared__ float4 sCoef[16];  // fused coef [c1][c2-half]: decay*(1+spec*mean)*g^|c1-c2|

    const int h1 = blockIdx.x >> 5;
    const int w1 = blockIdx.x & 31;
    const int t  = threadIdx.x;

    // Build fused 8x8 coefficient table for this (h1,w1) — closed form.
    if (t < 64) {
        const int c1 = t >> 3;
        const int c2 = t & 7;
        const float mean = geosum(h1, 32) * geosum(w1, 32) * geosum(c1, 8) * (1.0f / 8192.0f);
        const float coef = decay[c1] * (1.0f + spec_pe[c1 * 8 + c2] * mean)
                         * __powf(GAMMA, (float)abs(c1 - c2));
        reinterpret_cast<float*>(sCoef)[t] = coef;
    }

    // One thread per (h2,w2) c2-row: w2 = t&31, h2 = t>>5 (0..31).
    const int w2 = t & 31;
    const int h2 = t >> 5;
    const float s = __powf(GAMMA, (float)(abs(h1 - h2) + abs(w1 - w2)));

    __syncthreads();

    // Output slice for this (h1,w1): 65536 floats, contiguous.
    float* const pBase = out + (size_t)blockIdx.x * 65536 + ((size_t)t << 3);

    #pragma unroll
    for (int c1 = 0; c1 < 8; ++c1) {
        const float4 cfLo = sCoef[(c1 << 1) | 0];
        const float4 cfHi = sCoef[(c1 << 1) | 1];
        float* p = pBase + c1 * 8192;
        stg256wt(p, s * cfLo.x, s * cfLo.y, s * cfLo.z, s * cfLo.w,
                    s * cfHi.x, s * cfHi.y, s * cfHi.z, s * cfHi.w);
    }
}

extern "C" void kernel_launch(void* const* d_in, const int* in_sizes, int n_in,
                              void* d_out, int out_size) {
    // Inputs: x (unused, 524288 elems), decay (8), spec_pe (64) — identify by size.
    const float* decay   = nullptr;
    const float* spec_pe = nullptr;
    for (int i = 0; i < n_in; ++i) {
        if (in_sizes[i] == 8)       decay   = (const float*)d_in[i];
        else if (in_sizes[i] == 64) spec_pe = (const float*)d_in[i];
    }
    mrp3d_kernel<<<1024, 1024>>>(decay, spec_pe, (float*)d_out);
}